// round 5
// baseline (speedup 1.0000x reference)
#include <cuda_runtime.h>
#include <stdint.h>

#define GS 128            // grid dim
#define VX 132            // vol8 x-stride (padded from 129; 33 words)
#define VY 129
#define VZ 129
#define VTOT (VZ*VY*VX)   // 2,196,612 bytes

// Packed neighborhood volume: byte at (z,y,x) (z,y,x in [0,129))
// holds bits of grid[z-1+dz][y-1+dy][x-1+dx] (0 if OOB) at bit dz*4+dy*2+dx.
__device__ uint8_t  g_vol8[VTOT];
// Bitmask of grid: word (zz*128+yy)*4 + w has bit i = grid[zz][yy][32w+i] != 0.
__device__ uint32_t g_bits[GS*GS*4];

// ---- Kernel 1: pack binary grid into bitmask ----
// One float4 per thread (524288 threads -> full occupancy streaming).
// Each thread makes a 4-bit nibble; 8 lanes OR-combine via shfl_xor;
// lane%8==0 stores the 32-bit word.
__global__ void pack_bits_kernel(const float4* __restrict__ grid4) {
    int t = blockIdx.x * blockDim.x + threadIdx.x;   // 0 .. 524287
    float4 v = __ldg(grid4 + t);
    unsigned nib = (v.x != 0.0f ? 1u : 0u)
                 | (v.y != 0.0f ? 2u : 0u)
                 | (v.z != 0.0f ? 4u : 0u)
                 | (v.w != 0.0f ? 8u : 0u);
    unsigned word = nib << (4 * (threadIdx.x & 7));
    word |= __shfl_xor_sync(0xffffffffu, word, 1);
    word |= __shfl_xor_sync(0xffffffffu, word, 2);
    word |= __shfl_xor_sync(0xffffffffu, word, 4);
    if ((threadIdx.x & 7) == 0) g_bits[t >> 3] = word;
}

// ---- Kernel 2: build vol8 from the bitmask ----
// Each thread produces up to 32 consecutive-x bytes (chunk c of 5 per (z,y)
// row). Chunk 4 writes ONLY 1 word (x=128..131; 129-131 are pad) to avoid
// overflowing into the next row.
__global__ void build_vol8_kernel() {
    int id = blockIdx.x * blockDim.x + threadIdx.x;
    if (id >= VZ * VY * 5) return;
    int c = id % 5;
    int t = id / 5;
    int y = t % VY;
    int z = t / VY;
    int by = y - 1, bz = z - 1;

    // v[e] (e = dz*2+dy): 64-bit window of grid bits covering x = 32(c-1)..32c+31
    uint64_t v[4];
#pragma unroll
    for (int dz = 0; dz < 2; ++dz) {
        int zz = bz + dz;
#pragma unroll
        for (int dy = 0; dy < 2; ++dy) {
            int yy = by + dy;
            uint32_t lo = 0, hi = 0;
            if (zz >= 0 && zz < GS && yy >= 0 && yy < GS) {
                const uint32_t* row = &g_bits[(zz * GS + yy) * 4];
                if (c > 0) lo = __ldg(&row[c - 1]);
                if (c < 4) hi = __ldg(&row[c]);
            }
            v[dz * 2 + dy] = ((uint64_t)hi << 32) | (uint64_t)lo;
        }
    }

    // Output byte k (x_out = 32c+k) needs grid bits at x = x_out-1, x_out:
    // the 2-bit field of v[e] at position 31+k, placed at bit 2e of the byte.
    int nw = (c == 4) ? 1 : 8;
    uint32_t* dst = (uint32_t*)&g_vol8[(size_t)(z * VY + y) * VX + 32 * c];
#pragma unroll
    for (int w = 0; w < 8; ++w) {
        if (w >= nw) break;
        uint32_t acc = 0;
#pragma unroll
        for (int j = 0; j < 4; ++j) {
            int k = w * 4 + j;
            unsigned byte = 0;
#pragma unroll
            for (int e = 0; e < 4; ++e)
                byte |= (unsigned)((v[e] >> (31 + k)) & 3ull) << (2 * e);
            acc |= byte << (8 * j);
        }
        dst[w] = acc;
    }
}

// ---- Kernel 3: sample ----
__device__ __forceinline__ void coord_prep(float x, float y, float z,
                                           int& idx, float& wx, float& wy, float& wz) {
    float ix = ((x + 1.0f) * 128.0f - 1.0f) * 0.5f;
    float iy = ((y + 1.0f) * 128.0f - 1.0f) * 0.5f;
    float iz = ((z + 1.0f) * 128.0f - 1.0f) * 0.5f;
    float fx = floorf(ix), fy = floorf(iy), fz = floorf(iz);
    wx = ix - fx; wy = iy - fy; wz = iz - fz;
    int ix0 = (int)fx, iy0 = (int)fy, iz0 = (int)fz;
    // coords in [-1,1] -> base in [-1,127]; clamp only for memory safety
    ix0 = min(127, max(-1, ix0));
    iy0 = min(127, max(-1, iy0));
    iz0 = min(127, max(-1, iz0));
    idx = ((iz0 + 1) * VY + (iy0 + 1)) * VX + (ix0 + 1);
}

__device__ __forceinline__ float lerp_byte(unsigned b, float wx, float wy, float wz) {
    float f0 = (float)( b       & 1u);
    float f1 = (float)((b >> 1) & 1u);
    float f2 = (float)((b >> 2) & 1u);
    float f3 = (float)((b >> 3) & 1u);
    float f4 = (float)((b >> 4) & 1u);
    float f5 = (float)((b >> 5) & 1u);
    float f6 = (float)((b >> 6) & 1u);
    float f7 = (float)((b >> 7) & 1u);
    float c00 = fmaf(wx, f1 - f0, f0);
    float c10 = fmaf(wx, f3 - f2, f2);
    float c01 = fmaf(wx, f5 - f4, f4);
    float c11 = fmaf(wx, f7 - f6, f6);
    float c0  = fmaf(wy, c10 - c00, c00);
    float c1  = fmaf(wy, c11 - c01, c01);
    return fmaf(wz, c1 - c0, c0);
}

// 8 points per thread, register-disciplined:
//  - coords loaded in two 3xfloat4 halves so coord regs die early
//  - all 8 gathers issued back-to-back (MLP=8)
//  - __launch_bounds__(256,4) caps regs at 64 -> 4 blocks/SM, 32 warps,
//    256 outstanding gathers per SM.
__global__ void __launch_bounds__(256, 4)
sample_kernel(const float4* __restrict__ coords4,
              float4* __restrict__ out4, int n8) {
    int tid = blockIdx.x * blockDim.x + threadIdx.x;
    if (tid >= n8) return;
    const float4* p = coords4 + (size_t)tid * 6;

    int   idx[8];
    float wx[8], wy[8], wz[8];
    {
        float4 a = __ldg(p + 0);
        float4 b = __ldg(p + 1);
        float4 c = __ldg(p + 2);
        coord_prep(a.x, a.y, a.z, idx[0], wx[0], wy[0], wz[0]);
        coord_prep(a.w, b.x, b.y, idx[1], wx[1], wy[1], wz[1]);
        coord_prep(b.z, b.w, c.x, idx[2], wx[2], wy[2], wz[2]);
        coord_prep(c.y, c.z, c.w, idx[3], wx[3], wy[3], wz[3]);
    }
    {
        float4 d = __ldg(p + 3);
        float4 e = __ldg(p + 4);
        float4 f = __ldg(p + 5);
        coord_prep(d.x, d.y, d.z, idx[4], wx[4], wy[4], wz[4]);
        coord_prep(d.w, e.x, e.y, idx[5], wx[5], wy[5], wz[5]);
        coord_prep(e.z, e.w, f.x, idx[6], wx[6], wy[6], wz[6]);
        coord_prep(f.y, f.z, f.w, idx[7], wx[7], wy[7], wz[7]);
    }

    unsigned bv[8];
#pragma unroll
    for (int i = 0; i < 8; ++i) bv[i] = (unsigned)__ldg(&g_vol8[idx[i]]);

    float4 o0, o1;
    o0.x = lerp_byte(bv[0], wx[0], wy[0], wz[0]);
    o0.y = lerp_byte(bv[1], wx[1], wy[1], wz[1]);
    o0.z = lerp_byte(bv[2], wx[2], wy[2], wz[2]);
    o0.w = lerp_byte(bv[3], wx[3], wy[3], wz[3]);
    o1.x = lerp_byte(bv[4], wx[4], wy[4], wz[4]);
    o1.y = lerp_byte(bv[5], wx[5], wy[5], wz[5]);
    o1.z = lerp_byte(bv[6], wx[6], wy[6], wz[6]);
    o1.w = lerp_byte(bv[7], wx[7], wy[7], wz[7]);

    out4[(size_t)tid * 2 + 0] = o0;
    out4[(size_t)tid * 2 + 1] = o1;
}

extern "C" void kernel_launch(void* const* d_in, const int* in_sizes, int n_in,
                              void* d_out, int out_size) {
    const float* grid   = (const float*)d_in[0];   // 128^3 floats
    const float* coords = (const float*)d_in[1];   // N*3 floats
    float* out = (float*)d_out;                    // N floats

    // 1) pack grid -> bitmask (one float4 per thread, shuffle-combine)
    {
        int nthreads = GS * GS * GS / 4;           // 524,288
        pack_bits_kernel<<<nthreads / 256, 256>>>((const float4*)grid);
    }
    // 2) bitmask -> packed neighborhood volume
    {
        int total = VZ * VY * 5;                   // 83,205
        build_vol8_kernel<<<(total + 255) / 256, 256>>>();
    }
    // 3) sample
    {
        int n  = in_sizes[1] / 3;                  // 8,388,608
        int n8 = n / 8;                            // 1,048,576
        sample_kernel<<<n8 / 256, 256>>>((const float4*)coords,
                                         (float4*)out, n8);
    }
}

// round 6
// speedup vs baseline: 1.1835x; 1.1835x over previous
#include <cuda_runtime.h>
#include <stdint.h>

#define GS 128            // grid dim
#define VX 132            // vol8 x-stride (padded from 129; 33 words)
#define VY 129
#define VZ 129
#define VTOT (VZ*VY*VX)   // 2,196,612 bytes

// Packed neighborhood volume: byte at (z,y,x) (z,y,x in [0,129))
// holds bits of grid[z-1+dz][y-1+dy][x-1+dx] (0 if OOB) at bit dz*4+dy*2+dx.
__device__ uint8_t  g_vol8[VTOT];
// Bitmask of grid: word (zz*128+yy)*4 + w has bit i = grid[zz][yy][32w+i] != 0.
__device__ uint32_t g_bits[GS*GS*4];

// ---- Kernel 1: pack binary grid into bitmask ----
// One float4 per thread (524288 threads -> full-occupancy streaming).
// Each thread makes a 4-bit nibble; 8 lanes OR-combine via shfl_xor;
// lane%8==0 stores the 32-bit word.
__global__ void pack_bits_kernel(const float4* __restrict__ grid4) {
    int t = blockIdx.x * blockDim.x + threadIdx.x;   // 0 .. 524287
    float4 v = __ldcs(grid4 + t);
    unsigned nib = (v.x != 0.0f ? 1u : 0u)
                 | (v.y != 0.0f ? 2u : 0u)
                 | (v.z != 0.0f ? 4u : 0u)
                 | (v.w != 0.0f ? 8u : 0u);
    unsigned word = nib << (4 * (threadIdx.x & 7));
    word |= __shfl_xor_sync(0xffffffffu, word, 1);
    word |= __shfl_xor_sync(0xffffffffu, word, 2);
    word |= __shfl_xor_sync(0xffffffffu, word, 4);
    if ((threadIdx.x & 7) == 0) g_bits[t >> 3] = word;
}

// ---- Kernel 2: build vol8 from the bitmask ----
// Each thread produces up to 32 consecutive-x bytes (chunk c of 5 per (z,y)
// row). Chunk 4 writes ONLY 1 word (x=128..131; 129-131 are pad) to avoid
// overflowing into the next row.
__global__ void build_vol8_kernel() {
    int id = blockIdx.x * blockDim.x + threadIdx.x;
    if (id >= VZ * VY * 5) return;
    int c = id % 5;
    int t = id / 5;
    int y = t % VY;
    int z = t / VY;
    int by = y - 1, bz = z - 1;

    // v[e] (e = dz*2+dy): 64-bit window of grid bits covering x = 32(c-1)..32c+31
    uint64_t v[4];
#pragma unroll
    for (int dz = 0; dz < 2; ++dz) {
        int zz = bz + dz;
#pragma unroll
        for (int dy = 0; dy < 2; ++dy) {
            int yy = by + dy;
            uint32_t lo = 0, hi = 0;
            if (zz >= 0 && zz < GS && yy >= 0 && yy < GS) {
                const uint32_t* row = &g_bits[(zz * GS + yy) * 4];
                if (c > 0) lo = __ldg(&row[c - 1]);
                if (c < 4) hi = __ldg(&row[c]);
            }
            v[dz * 2 + dy] = ((uint64_t)hi << 32) | (uint64_t)lo;
        }
    }

    // Output byte k (x_out = 32c+k) needs grid bits at x = x_out-1, x_out:
    // the 2-bit field of v[e] at position 31+k, placed at bit 2e of the byte.
    int nw = (c == 4) ? 1 : 8;
    uint32_t* dst = (uint32_t*)&g_vol8[(size_t)(z * VY + y) * VX + 32 * c];
#pragma unroll
    for (int w = 0; w < 8; ++w) {
        if (w >= nw) break;
        uint32_t acc = 0;
#pragma unroll
        for (int j = 0; j < 4; ++j) {
            int k = w * 4 + j;
            unsigned byte = 0;
#pragma unroll
            for (int e = 0; e < 4; ++e)
                byte |= (unsigned)((v[e] >> (31 + k)) & 3ull) << (2 * e);
            acc |= byte << (8 * j);
        }
        dst[w] = acc;
    }
}

// ---- Kernel 3: sample (R1 structure: interleaved, 4 pts/thread, ~30 regs) ----
__device__ __forceinline__ float sample_one(float x, float y, float z) {
    float ix = ((x + 1.0f) * 128.0f - 1.0f) * 0.5f;
    float iy = ((y + 1.0f) * 128.0f - 1.0f) * 0.5f;
    float iz = ((z + 1.0f) * 128.0f - 1.0f) * 0.5f;
    float fx = floorf(ix), fy = floorf(iy), fz = floorf(iz);
    float wx = ix - fx, wy = iy - fy, wz = iz - fz;
    int ix0 = (int)fx, iy0 = (int)fy, iz0 = (int)fz;
    // coords in [-1,1] -> base in [-1,127]; clamp only for memory safety
    ix0 = min(127, max(-1, ix0));
    iy0 = min(127, max(-1, iy0));
    iz0 = min(127, max(-1, iz0));
    int idx = ((iz0 + 1) * VY + (iy0 + 1)) * VX + (ix0 + 1);
    unsigned b = (unsigned)__ldg(&g_vol8[idx]);

    float f0 = (float)( b       & 1u);
    float f1 = (float)((b >> 1) & 1u);
    float f2 = (float)((b >> 2) & 1u);
    float f3 = (float)((b >> 3) & 1u);
    float f4 = (float)((b >> 4) & 1u);
    float f5 = (float)((b >> 5) & 1u);
    float f6 = (float)((b >> 6) & 1u);
    float f7 = (float)((b >> 7) & 1u);

    float c00 = fmaf(wx, f1 - f0, f0);
    float c10 = fmaf(wx, f3 - f2, f2);
    float c01 = fmaf(wx, f5 - f4, f4);
    float c11 = fmaf(wx, f7 - f6, f6);
    float c0  = fmaf(wy, c10 - c00, c00);
    float c1  = fmaf(wy, c11 - c01, c01);
    return fmaf(wz, c1 - c0, c0);
}

// 4 points per thread; coords/out use streaming hints (evict-first) so the
// 2.2MB vol8 table keeps L1 residency for the gathers.
__global__ void sample_kernel(const float4* __restrict__ coords4,
                              float4* __restrict__ out4, int n4) {
    int tid = blockIdx.x * blockDim.x + threadIdx.x;
    if (tid >= n4) return;
    float4 a = __ldcs(&coords4[(size_t)tid * 3 + 0]);
    float4 b = __ldcs(&coords4[(size_t)tid * 3 + 1]);
    float4 c = __ldcs(&coords4[(size_t)tid * 3 + 2]);

    float4 o;
    o.x = sample_one(a.x, a.y, a.z);
    o.y = sample_one(a.w, b.x, b.y);
    o.z = sample_one(b.z, b.w, c.x);
    o.w = sample_one(c.y, c.z, c.w);
    __stcs(&out4[tid], o);
}

extern "C" void kernel_launch(void* const* d_in, const int* in_sizes, int n_in,
                              void* d_out, int out_size) {
    const float* grid   = (const float*)d_in[0];   // 128^3 floats
    const float* coords = (const float*)d_in[1];   // N*3 floats
    float* out = (float*)d_out;                    // N floats

    // 1) pack grid -> bitmask (one float4 per thread, shuffle-combine)
    {
        int nthreads = GS * GS * GS / 4;           // 524,288
        pack_bits_kernel<<<nthreads / 256, 256>>>((const float4*)grid);
    }
    // 2) bitmask -> packed neighborhood volume
    {
        int total = VZ * VY * 5;                   // 83,205
        build_vol8_kernel<<<(total + 255) / 256, 256>>>();
    }
    // 3) sample
    {
        int n  = in_sizes[1] / 3;                  // 8,388,608
        int n4 = n / 4;                            // 2,097,152
        sample_kernel<<<n4 / 256, 256>>>((const float4*)coords,
                                         (float4*)out, n4);
    }
}